// round 3
// baseline (speedup 1.0000x reference)
#include <cuda_runtime.h>
#include <cuda_bf16.h>

// SmoothLDDTLoss, B=2, N=4096 — single fused kernel, f32x2-packed mainloop.
//
// Math:
//  - c_lm mask == ~eye(N)  (nuc | ~nuc)  -> is_dna/is_rna dead, denom constant.
//  - 0.25*sum of 4 sigmoids, in u = e^{-delta} = 2^{-|r|} (no overflow, no clamp):
//      eps = u*(((u+PC1)u+PC2)u+PC3) / ((((u+QC1)u+QC2)u+QC3)u+QC4)
//  - r = log2e*(dGT - dx) via expanded form with per-point precomputed norms.
//  - symmetry: upper-triangular tiles, x2 at the end.
//  - two m-points per iteration, all polynomial math in packed f32x2.

constexpr int N    = 4096;
constexpr int B    = 2;
constexpr int TILE = 128;
constexpr int NT   = N / TILE;           // 32
constexpr int TRI  = NT * (NT + 1) / 2;  // 528
constexpr int GRID = TRI * B;            // 1056

#define QC1 1.1280610230f
#define QC2 0.3753279229f
#define QC3 0.0366994760f
#define QC4 0.0005530844f
#define PC1 0.8460457673f   // 0.75*QC1
#define PC2 0.1876639614f   // 0.50*QC2
#define PC3 0.0091748690f   // 0.25*QC3
#define LOG2E 1.4426950408889634f

typedef unsigned long long ull;

#define FMA2(d,a,b,c) asm("fma.rn.f32x2 %0, %1, %2, %3;" : "=l"(d) : "l"(a), "l"(b), "l"(c))
#define ADD2(d,a,b)   asm("add.rn.f32x2 %0, %1, %2;"     : "=l"(d) : "l"(a), "l"(b))
#define MUL2(d,a,b)   asm("mul.rn.f32x2 %0, %1, %2;"     : "=l"(d) : "l"(a), "l"(b))

__device__ __forceinline__ ull pack2(float a, float b) {
    ull r; asm("mov.b64 %0, {%1, %2};" : "=l"(r) : "f"(a), "f"(b)); return r;
}
__device__ __forceinline__ void unpack2(ull v, float& a, float& b) {
    asm("mov.b64 {%0, %1}, %2;" : "=f"(a), "=f"(b) : "l"(v));
}

__device__ float        g_part[GRID];
__device__ unsigned int g_cnt = 0;

// scalar path (diagonal tiles only)
__device__ __forceinline__ float eps_scalar(float r) {
    float u; asm("ex2.approx.f32 %0, %1;" : "=f"(u) : "f"(-fabsf(r)));
    float nm = ((u + PC1) * u + PC2) * u + PC3;
    nm *= u;
    float dq = fmaf(fmaf(fmaf((u + QC1), u, QC2), u, QC3), u, QC4);
    float iq; asm("rcp.approx.f32 %0, %1;" : "=f"(iq) : "f"(dq));
    return nm * iq;
}

__global__ __launch_bounds__(TILE) void lddt_k(const float* __restrict__ x,
                                               const float* __restrict__ xgt,
                                               float* __restrict__ out) {
    const int p = blockIdx.x;
    const int b = p / TRI;
    int rem = p - b * TRI;
    int bi = 0;
    while (rem >= NT - bi) { rem -= NT - bi; ++bi; }
    const int bj = bi + rem;

    const float* xb = x   + (size_t)b * N * 3;
    const float* gb = xgt + (size_t)b * N * 3;
    const int t = threadIdx.x;

    // SoA tile: rows = {2L*gx, 2L*gy, 2L*gz, L*(|g|^2-|x|^2), 2L*xx, 2L*xy, 2L*xz}
    __shared__ float sm[7][TILE];

    {
        const int mg = bj * TILE + t;
        float mx0 = xb[3*mg], mx1 = xb[3*mg+1], mx2 = xb[3*mg+2];
        float mg0 = gb[3*mg], mg1 = gb[3*mg+1], mg2 = gb[3*mg+2];
        float s = fmaf(mg0, mg0, fmaf(mg1, mg1, mg2*mg2))
                - fmaf(mx0, mx0, fmaf(mx1, mx1, mx2*mx2));
        sm[0][t] = 2.0f*LOG2E*mg0;  sm[1][t] = 2.0f*LOG2E*mg1;  sm[2][t] = 2.0f*LOG2E*mg2;
        sm[3][t] = LOG2E*s;
        sm[4][t] = 2.0f*LOG2E*mx0;  sm[5][t] = 2.0f*LOG2E*mx1;  sm[6][t] = 2.0f*LOG2E*mx2;
    }

    const int lg = bi * TILE + t;
    const float lx0 = xb[3*lg], lx1 = xb[3*lg+1], lx2 = xb[3*lg+2];
    const float lg0 = gb[3*lg], lg1 = gb[3*lg+1], lg2 = gb[3*lg+2];
    const float sLl = LOG2E * (fmaf(lg0, lg0, fmaf(lg1, lg1, lg2*lg2))
                             - fmaf(lx0, lx0, fmaf(lx1, lx1, lx2*lx2)));
    __syncthreads();

    float acc;
    if (bi != bj) {
        // pack loop-invariant operands
        const ull ngx = pack2(-lg0, -lg0), ngy = pack2(-lg1, -lg1), ngz = pack2(-lg2, -lg2);
        const ull pxx = pack2( lx0,  lx0), pxy = pack2( lx1,  lx1), pxz = pack2( lx2,  lx2);
        const ull sl2 = pack2(sLl, sLl);
        const ull pc1 = pack2(PC1, PC1), pc2 = pack2(PC2, PC2), pc3 = pack2(PC3, PC3);
        const ull qc1 = pack2(QC1, QC1), qc2 = pack2(QC2, QC2),
                  qc3 = pack2(QC3, QC3), qc4 = pack2(QC4, QC4);
        ull acc2 = 0ull;   // {0.0f, 0.0f}

#pragma unroll 4
        for (int k = 0; k < TILE / 2; ++k) {
            const ull agx = *(const ull*)&sm[0][2*k];
            const ull agy = *(const ull*)&sm[1][2*k];
            const ull agz = *(const ull*)&sm[2][2*k];
            const ull aw  = *(const ull*)&sm[3][2*k];
            const ull abx = *(const ull*)&sm[4][2*k];
            const ull aby = *(const ull*)&sm[5][2*k];
            const ull abz = *(const ull*)&sm[6][2*k];

            ull r; ADD2(r, sl2, aw);
            FMA2(r, ngx, agx, r);
            FMA2(r, ngy, agy, r);
            FMA2(r, ngz, agz, r);
            FMA2(r, pxx, abx, r);
            FMA2(r, pxy, aby, r);
            FMA2(r, pxz, abz, r);

            float r0, r1;  unpack2(r, r0, r1);
            float u0, u1;
            asm("ex2.approx.f32 %0, %1;" : "=f"(u0) : "f"(-fabsf(r0)));
            asm("ex2.approx.f32 %0, %1;" : "=f"(u1) : "f"(-fabsf(r1)));
            const ull u = pack2(u0, u1);

            ull nm; ADD2(nm, u, pc1);
            FMA2(nm, nm, u, pc2);
            FMA2(nm, nm, u, pc3);
            MUL2(nm, nm, u);

            ull dq; ADD2(dq, u, qc1);
            FMA2(dq, dq, u, qc2);
            FMA2(dq, dq, u, qc3);
            FMA2(dq, dq, u, qc4);

            float q0, q1;  unpack2(dq, q0, q1);
            float i0, i1;
            asm("rcp.approx.f32 %0, %1;" : "=f"(i0) : "f"(q0));
            asm("rcp.approx.f32 %0, %1;" : "=f"(i1) : "f"(q1));
            const ull iq = pack2(i0, i1);

            FMA2(acc2, nm, iq, acc2);
        }
        float a0, a1;  unpack2(acc2, a0, a1);
        acc = a0 + a1;
    } else {
        // diagonal tile: scalar with strict-upper predicate (64 of 1056 blocks)
        acc = 0.f;
#pragma unroll 4
        for (int m = 0; m < TILE; ++m) {
            float r = sLl + sm[3][m];
            r = fmaf(lg0, -sm[0][m], r);
            r = fmaf(lg1, -sm[1][m], r);
            r = fmaf(lg2, -sm[2][m], r);
            r = fmaf(lx0,  sm[4][m], r);
            r = fmaf(lx1,  sm[5][m], r);
            r = fmaf(lx2,  sm[6][m], r);
            float e = eps_scalar(r);
            if (m > t) acc += e;
        }
    }

    // block reduce
#pragma unroll
    for (int o = 16; o > 0; o >>= 1)
        acc += __shfl_xor_sync(0xffffffffu, acc, o);

    __shared__ float ws[TILE / 32];
    __shared__ bool  is_last;
    if ((t & 31) == 0) ws[t >> 5] = acc;
    __syncthreads();
    if (t == 0) {
        g_part[p] = ws[0] + ws[1] + ws[2] + ws[3];
        __threadfence();
        unsigned old = atomicAdd(&g_cnt, 1u);
        is_last = (old == GRID - 1);
    }
    __syncthreads();

    if (is_last) {
        float s = 0.f;
        for (int i = t; i < GRID; i += TILE)
            s += *((volatile float*)&g_part[i]);
#pragma unroll
        for (int o = 16; o > 0; o >>= 1)
            s += __shfl_xor_sync(0xffffffffu, s, o);
        if ((t & 31) == 0) ws[t >> 5] = s;
        __syncthreads();
        if (t == 0) {
            double S = (double)ws[0] + ws[1] + ws[2] + ws[3];
            const double cnt = (double)B * N * (N - 1);   // 33,546,240
            out[0] = (float)(1.0 - 2.0 * S / cnt);
            g_cnt = 0;   // reset for next graph replay
        }
    }
}

extern "C" void kernel_launch(void* const* d_in, const int* in_sizes, int n_in,
                              void* d_out, int out_size) {
    const float* x   = (const float*)d_in[0];
    const float* xgt = (const float*)d_in[1];
    // d_in[2] (is_dna), d_in[3] (is_rna) are provably dead: c_lm == ~eye(N).
    lddt_k<<<GRID, TILE>>>(x, xgt, (float*)d_out);
}